// round 4
// baseline (speedup 1.0000x reference)
#include <cuda_runtime.h>

#define BB    4
#define NN    2304
#define CC    64
#define NODE_ 48
#define KTOP  11          // K_NEIGS + 1
#define NWIN  22
#define NLOC  484         // 22*22 local hyperedges
#define EPB   (NN + NLOC) // edges per batch = 2788
#define BN    (BB * NN)   // 9216
#define MSEL  32          // cached top-M per row (fast path)
#define BNEPS 1e-5f

typedef unsigned long long ull;

// ---------------- scratch (static device globals; no allocation) -------------
__device__ unsigned g_du[(size_t)BB * NN * NN]; // ordered-uint distance matrix
__device__ int   g_mem[(size_t)BB * NN * NN];   // slow-path member lists (K>MSEL)
__device__ int   g_top[(size_t)BN * MSEL];      // fast-path sorted top-M indices
__device__ int   g_cnt1[BN];                    // Dv: in-degree of 11-NN graph
__device__ int   g_cnt2[BN];                    // knn part of total node degree
__device__ float g_xsq[BN];
__device__ float g_dv2[BN];                     // DV^-0.5
__device__ float g_z[BN * CC];                  // dv2 * (xW^T + b)
__device__ float g_y[BN * CC];                  // conv output
__device__ float g_bns[2 * CC];                 // BN sum / sumsq

// ---------------- zero pass --------------------------------------------------
__global__ void k_zero() {
    int i = blockIdx.x * blockDim.x + threadIdx.x;
    int stride = gridDim.x * blockDim.x;
    for (int k = i; k < BN * CC; k += stride) g_y[k] = 0.f;
    for (int k = i; k < BN; k += stride) { g_cnt1[k] = 0; g_cnt2[k] = 0; }
    if (i < 2 * CC) g_bns[i] = 0.f;
}

// ---------------- row squared norms -----------------------------------------
__global__ void k_xsq(const float* __restrict__ x) {
    int w = (blockIdx.x * blockDim.x + threadIdx.x) >> 5;
    int lane = threadIdx.x & 31;
    if (w >= BN) return;
    float a = x[w * CC + lane];
    float b = x[w * CC + 32 + lane];
    float s = a * a + b * b;
    #pragma unroll
    for (int o = 16; o; o >>= 1) s += __shfl_down_sync(0xffffffffu, s, o);
    if (lane == 0) g_xsq[w] = s;
}

// float -> order-preserving uint32
__device__ __forceinline__ unsigned fkey(float v) {
    unsigned u = __float_as_uint(v);
    return u ^ ((unsigned)((int)u >> 31) | 0x80000000u);
}

// ---------------- pairwise squared distances: upper triangle only ------------
__global__ void __launch_bounds__(64) k_dist(const float* __restrict__ x) {
    __shared__ float As[64 * 68];
    __shared__ float Bs[64 * 68];
    __shared__ float sxi[64], sxj[64];
    int b = blockIdx.y;
    int t = blockIdx.x;
    int ti = 0;
    while (t >= 36 - ti) { t -= 36 - ti; ti++; }
    int tj = ti + t;
    int i0 = ti * 64, j0 = tj * 64;
    const float* xb = x + (size_t)b * NN * CC;
    int tid = threadIdx.x;

    for (int k = tid; k < 64 * 16; k += 64) {
        int r = k >> 4, c4 = (k & 15) << 2;
        *(float4*)(&As[r * 68 + c4]) = *(const float4*)(xb + (size_t)(i0 + r) * CC + c4);
        *(float4*)(&Bs[r * 68 + c4]) = *(const float4*)(xb + (size_t)(j0 + r) * CC + c4);
    }
    sxi[tid] = g_xsq[b * NN + i0 + tid];
    sxj[tid] = g_xsq[b * NN + j0 + tid];
    __syncthreads();

    int tx = tid & 7, ty = tid >> 3;
    float acc[8][8];
    #pragma unroll
    for (int i = 0; i < 8; i++)
        #pragma unroll
        for (int j = 0; j < 8; j++) acc[i][j] = 0.f;

    #pragma unroll 2
    for (int c = 0; c < 64; c += 4) {
        float4 a[8], bb[8];
        #pragma unroll
        for (int u = 0; u < 8; u++) {
            a[u]  = *(const float4*)(&As[(ty + 8 * u) * 68 + c]);
            bb[u] = *(const float4*)(&Bs[(tx + 8 * u) * 68 + c]);
        }
        #pragma unroll
        for (int i = 0; i < 8; i++)
            #pragma unroll
            for (int j = 0; j < 8; j++)
                acc[i][j] += a[i].x * bb[j].x + a[i].y * bb[j].y +
                             a[i].z * bb[j].z + a[i].w * bb[j].w;
    }

    float xi[8], xj[8];
    #pragma unroll
    for (int u = 0; u < 8; u++) { xi[u] = sxi[ty + 8 * u]; xj[u] = sxj[tx + 8 * u]; }
    __syncthreads();
    unsigned* S = (unsigned*)As;           // 64x65 staging
    #pragma unroll
    for (int i = 0; i < 8; i++)
        #pragma unroll
        for (int j = 0; j < 8; j++) {
            float v = (xi[i] - 2.f * acc[i][j]) + xj[j];
            S[(ty + 8 * i) * 65 + (tx + 8 * j)] = fkey(v);
        }
    __syncthreads();

    unsigned* dd = g_du + (size_t)b * NN * NN;
    #pragma unroll 4
    for (int r = 0; r < 64; r++)
        dd[(size_t)(i0 + r) * NN + j0 + tid] = S[r * 65 + tid];
    if (ti != tj) {
        #pragma unroll 4
        for (int r = 0; r < 64; r++)
            dd[(size_t)(j0 + r) * NN + i0 + tid] = S[tid * 65 + r];
    }
}

// ---------------- warp-level streaming top-K select --------------------------
#define SENT 0xffffffffffffffffULL

__device__ __forceinline__ void ins4(ull& k1, ull& k2, ull& k3, ull& k4, ull key) {
    if (key < k4) {
        if (key < k3) {
            k4 = k3;
            if (key < k2) {
                k3 = k2;
                if (key < k1) { k2 = k1; k1 = key; } else k2 = key;
            } else k3 = key;
        } else k4 = key;
    }
}

// warp-wide u64 min via two hardware redux.sync ops (exact (value,index) order)
__device__ __forceinline__ ull warp_min64(ull k) {
    unsigned hi = (unsigned)(k >> 32);
    unsigned bhi = __reduce_min_sync(0xffffffffu, hi);
    unsigned lo = (hi == bhi) ? (unsigned)k : 0xffffffffu;
    unsigned blo = __reduce_min_sync(0xffffffffu, lo);
    return ((ull)bhi << 32) | blo;
}

// K extractions, smallest-first by (value, index). Per extracted idx calls SINK.
// Scan is gated: cheap u32 min-of-4 test skips chunks that cannot enter the
// per-lane top-4 cache; <= keeps exact tie semantics (u64 compare decides).
template <class SINK>
__device__ __forceinline__ void run_select(int row, int lane, int K, SINK sink) {
    const unsigned* dr = g_du + (size_t)row * NN;
    ull k1 = SENT, k2 = SENT, k3 = SENT, k4 = SENT;
    unsigned th = 0xffffffffu;
    #pragma unroll 1
    for (int t = 0; t < 18; t++) {
        int base = t * 128 + lane * 4;
        uint4 v = *(const uint4*)(dr + base);
        unsigned mn = min(min(v.x, v.y), min(v.z, v.w));
        if (mn <= th) {
            if (v.x <= th) { ins4(k1, k2, k3, k4, ((ull)v.x << 32) | (unsigned)(base + 0)); th = (unsigned)(k4 >> 32); }
            if (v.y <= th) { ins4(k1, k2, k3, k4, ((ull)v.y << 32) | (unsigned)(base + 1)); th = (unsigned)(k4 >> 32); }
            if (v.z <= th) { ins4(k1, k2, k3, k4, ((ull)v.z << 32) | (unsigned)(base + 2)); th = (unsigned)(k4 >> 32); }
            if (v.w <= th) { ins4(k1, k2, k3, k4, ((ull)v.w << 32) | (unsigned)(base + 3)); th = (unsigned)(k4 >> 32); }
        }
    }
    ull last = 0;
    for (int it = 0; it < K; it++) {
        bool need = (k1 == SENT);
        if (__ballot_sync(0xffffffffu, need)) {
            if (need) {
                k1 = k2 = k3 = k4 = SENT;
                th = 0xffffffffu;
                unsigned lasthi = (unsigned)(last >> 32);
                #pragma unroll 1
                for (int t = 0; t < 18; t++) {
                    int base = t * 128 + lane * 4;
                    uint4 v = *(const uint4*)(dr + base);
                    unsigned mn = min(min(v.x, v.y), min(v.z, v.w));
                    if (mn <= th) {
                        ull a = ((ull)v.x << 32) | (unsigned)(base + 0);
                        ull b = ((ull)v.y << 32) | (unsigned)(base + 1);
                        ull c = ((ull)v.z << 32) | (unsigned)(base + 2);
                        ull d = ((ull)v.w << 32) | (unsigned)(base + 3);
                        if (v.x <= th && a > last) { ins4(k1, k2, k3, k4, a); th = (unsigned)(k4 >> 32); }
                        if (v.y <= th && b > last) { ins4(k1, k2, k3, k4, b); th = (unsigned)(k4 >> 32); }
                        if (v.z <= th && c > last) { ins4(k1, k2, k3, k4, c); th = (unsigned)(k4 >> 32); }
                        if (v.w <= th && d > last) { ins4(k1, k2, k3, k4, d); th = (unsigned)(k4 >> 32); }
                    }
                    (void)lasthi;
                }
            }
        }
        ull bst = warp_min64(k1);
        last = bst;
        if (k1 == bst) { k1 = k2; k2 = k3; k3 = k4; k4 = SENT; }
        if (lane == 0) sink(it, (int)(unsigned)bst);
    }
}

// fast path: extract MSEL smallest per row; store list; count in-degree (top-11)
__global__ void __launch_bounds__(256) k_select() {
    int row  = blockIdx.x * 8 + (threadIdx.x >> 5);
    int lane = threadIdx.x & 31;
    int nb   = (row / NN) * NN;
    run_select(row, lane, MSEL, [&](int it, int bi) {
        g_top[(size_t)row * MSEL + it] = bi;
        if (it < KTOP) atomicAdd(&g_cnt1[nb + bi], 1);
    });
}

// cnt2 counting; rows with K > MSEL re-select fully into g_mem (slow path)
__global__ void __launch_bounds__(256) k_cnt2slow() {
    int row  = blockIdx.x * 8 + (threadIdx.x >> 5);
    int lane = threadIdx.x & 31;
    int K  = g_cnt1[row];
    int nb = (row / NN) * NN;
    if (K <= MSEL) {
        const int* lst = g_top + (size_t)row * MSEL;
        for (int t = lane; t < K; t += 32) atomicAdd(&g_cnt2[nb + lst[t]], 1);
    } else {
        int* out = g_mem + (size_t)row * NN;
        run_select(row, lane, K, [&](int it, int bi) {
            out[it] = bi;
            atomicAdd(&g_cnt2[nb + bi], 1);
        });
    }
}

// ---------------- node normalization factors ---------------------------------
__device__ __forceinline__ int coverc(int r) {
    int lo = r - 4; if (lo < 0) lo = 0;
    int hi = r;     if (hi > 42) hi = 42;
    if (hi < lo) return 0;
    return hi / 2 - (lo + 1) / 2 + 1;
}

__global__ void k_dv2() {
    int i = blockIdx.x * blockDim.x + threadIdx.x;
    if (i >= BN) return;
    int n = i % NN;
    int deg = g_cnt2[i] + coverc(n / NODE_) * coverc(n % NODE_);
    g_dv2[i] = rsqrtf((float)deg);
}

// ---------------- z = dv2 * (x W^T + b) --------------------------------------
__global__ void __launch_bounds__(256) k_z(const float* __restrict__ x,
                                           const float* __restrict__ W,
                                           const float* __restrict__ bias) {
    __shared__ float Ws[64][65];
    __shared__ float xs[32][65];
    __shared__ float sb[64];
    int tid = threadIdx.x;
    int base = blockIdx.x * 32;
    for (int k = tid; k < 64 * 64; k += 256) Ws[k >> 6][k & 63] = W[k];
    for (int k = tid; k < 32 * 64; k += 256) xs[k >> 6][k & 63] = x[(size_t)(base + (k >> 6)) * CC + (k & 63)];
    if (tid < 64) sb[tid] = bias[tid];
    __syncthreads();

    int o = tid & 63, rg = tid >> 6;
    for (int r = rg; r < 32; r += 4) {
        float acc = sb[o];
        #pragma unroll
        for (int c = 0; c < 64; c++) acc += xs[r][c] * Ws[o][c];
        int row = base + r;
        g_z[(size_t)row * CC + o] = g_dv2[row] * acc;
    }
}

// ---------------- hyperedge gather / mean / scatter --------------------------
__global__ void __launch_bounds__(64) k_edge() {
    __shared__ int   sm[128];
    __shared__ float sdv[128];
    int e = blockIdx.x;
    int b = e / EPB;
    int le = e % EPB;
    int tid = threadIdx.x;
    int bNN = b * NN;
    int m;
    const int* lst = 0;
    if (le < NN) {
        int row = bNN + le;
        m = g_cnt1[row];
        lst = (m <= MSEL) ? (g_top + (size_t)row * MSEL) : (g_mem + (size_t)row * NN);
    } else {
        m = 25;
    }

    if (m <= 128) {
        if (le < NN) {
            for (int t = tid; t < m; t += 64) {
                int mi = lst[t];
                sm[t] = mi;
                sdv[t] = g_dv2[bNN + mi];
            }
        } else {
            int l = le - NN;
            int wi = l / NWIN, wj = l % NWIN;
            if (tid < 25) {
                int mi = (2 * wi + tid / 5) * NODE_ + (2 * wj + tid % 5);
                sm[tid] = mi;
                sdv[tid] = g_dv2[bNN + mi];
            }
        }
        __syncthreads();
        float acc = 0.f;
        for (int t = 0; t < m; t++)
            acc += g_z[((size_t)(bNN + sm[t])) * CC + tid];
        float u = acc * (1.0f / (float)m);
        for (int t = 0; t < m; t++)
            atomicAdd(&g_y[((size_t)(bNN + sm[t])) * CC + tid], sdv[t] * u);
    } else {
        float acc = 0.f;
        for (int base = 0; base < m; base += 128) {
            int cnt = min(128, m - base);
            __syncthreads();
            for (int t = tid; t < cnt; t += 64) sm[t] = lst[base + t];
            __syncthreads();
            for (int t = 0; t < cnt; t++)
                acc += g_z[((size_t)(bNN + sm[t])) * CC + tid];
        }
        float u = acc * (1.0f / (float)m);
        for (int base = 0; base < m; base += 128) {
            int cnt = min(128, m - base);
            __syncthreads();
            for (int t = tid; t < cnt; t += 64) {
                int mi = lst[base + t];
                sm[t] = mi;
                sdv[t] = g_dv2[bNN + mi];
            }
            __syncthreads();
            for (int t = 0; t < cnt; t++)
                atomicAdd(&g_y[((size_t)(bNN + sm[t])) * CC + tid], sdv[t] * u);
        }
    }
}

// ---------------- batchnorm statistics ---------------------------------------
__global__ void __launch_bounds__(256) k_bnstat() {
    __shared__ float red[256];
    int tid = threadIdx.x;
    int c = tid & 63, rg = tid >> 6;
    int r0 = blockIdx.x * 192;
    float s = 0.f, sq = 0.f;
    for (int r = r0 + rg; r < r0 + 192; r += 4) {
        float v = g_y[(size_t)r * CC + c];
        s += v; sq += v * v;
    }
    red[tid] = s; __syncthreads();
    if (rg == 0) atomicAdd(&g_bns[c], red[tid] + red[tid + 64] + red[tid + 128] + red[tid + 192]);
    __syncthreads();
    red[tid] = sq; __syncthreads();
    if (rg == 0) atomicAdd(&g_bns[64 + c], red[tid] + red[tid + 64] + red[tid + 128] + red[tid + 192]);
}

// ---------------- normalize + relu + residual --------------------------------
__global__ void __launch_bounds__(256) k_final(const float* __restrict__ x,
                                               const float* __restrict__ gamma,
                                               const float* __restrict__ beta,
                                               float* __restrict__ out) {
    __shared__ float sscale[64], sshift[64];
    int tid = threadIdx.x;
    if (tid < 64) {
        float mean = g_bns[tid] * (1.f / (float)BN);
        float var = g_bns[64 + tid] * (1.f / (float)BN) - mean * mean;
        float inv = rsqrtf(var + BNEPS);
        sscale[tid] = gamma[tid] * inv;
        sshift[tid] = beta[tid] - gamma[tid] * mean * inv;
    }
    __syncthreads();
    int idx = blockIdx.x * 256 + tid;
    int c = idx & 63;
    float v = g_y[idx] * sscale[c] + sshift[c];
    out[idx] = fmaxf(v, 0.f) + x[idx];
}

// ---------------- launch -----------------------------------------------------
extern "C" void kernel_launch(void* const* d_in, const int* in_sizes, int n_in,
                              void* d_out, int out_size) {
    const float* x     = (const float*)d_in[0];
    const float* W     = (const float*)d_in[1];
    const float* bias  = (const float*)d_in[2];
    const float* gamma = (const float*)d_in[3];
    const float* beta  = (const float*)d_in[4];
    float* out = (float*)d_out;
    (void)in_sizes; (void)n_in; (void)out_size;

    k_zero<<<512, 256>>>();
    k_xsq<<<(BN * 32) / 256, 256>>>(x);
    k_dist<<<dim3(666, BB), 64>>>(x);
    k_select<<<BN / 8, 256>>>();
    k_cnt2slow<<<BN / 8, 256>>>();
    k_dv2<<<(BN + 255) / 256, 256>>>();
    k_z<<<BN / 32, 256>>>(x, W, bias);
    k_edge<<<BB * EPB, 64>>>();
    k_bnstat<<<48, 256>>>();
    k_final<<<(BN * CC) / 256, 256>>>(x, gamma, beta, out);
}

// round 5
// speedup vs baseline: 1.0824x; 1.0824x over previous
#include <cuda_runtime.h>

#define BB    4
#define NN    2304
#define CC    64
#define NODE_ 48
#define KTOP  11          // K_NEIGS + 1
#define NWIN  22
#define NLOC  484         // 22*22 local hyperedges
#define EPB   (NN + NLOC) // edges per batch = 2788
#define BN    (BB * NN)   // 9216
#define MSEL  32          // cached top-M per row (fast path)
#define BNEPS 1e-5f

typedef unsigned long long ull;

// ---------------- scratch (static device globals; no allocation) -------------
__device__ unsigned g_du[(size_t)BB * NN * NN]; // ordered-uint distance matrix
__device__ int   g_mem[(size_t)BB * NN * NN];   // slow-path member lists (K>MSEL)
__device__ int   g_top[(size_t)BN * MSEL];      // fast-path sorted top-M indices
__device__ int   g_cnt1[BN];                    // Dv: in-degree of 11-NN graph
__device__ int   g_cnt2[BN];                    // knn part of total node degree
__device__ float g_xsq[BN];
__device__ float g_dv2[BN];                     // DV^-0.5
__device__ float g_z[BN * CC];                  // dv2 * (xW^T + b)
__device__ float g_y[BN * CC];                  // conv output
__device__ float g_bns[2 * CC];                 // BN sum / sumsq

// ---------------- init: row norms + zeroing (fused) --------------------------
__global__ void __launch_bounds__(256) k_init(const float* __restrict__ x) {
    int idx = blockIdx.x * 256 + threadIdx.x;    // 1152 blocks -> 294912 threads
    int w = idx >> 5, lane = idx & 31;           // warp per row, w < BN
    float a = x[w * CC + lane];
    float b = x[w * CC + 32 + lane];
    float s = a * a + b * b;
    #pragma unroll
    for (int o = 16; o; o >>= 1) s += __shfl_down_sync(0xffffffffu, s, o);
    if (lane == 0) g_xsq[w] = s;
    g_y[idx] = 0.f;
    g_y[idx + 294912] = 0.f;                     // BN*CC = 2 * 294912
    if (idx < BN) { g_cnt1[idx] = 0; g_cnt2[idx] = 0; }
    if (idx < 2 * CC) g_bns[idx] = 0.f;
}

// float -> order-preserving uint32
__device__ __forceinline__ unsigned fkey(float v) {
    unsigned u = __float_as_uint(v);
    return u ^ ((unsigned)((int)u >> 31) | 0x80000000u);
}

// ---------------- pairwise squared distances: upper triangle only ------------
__global__ void __launch_bounds__(64) k_dist(const float* __restrict__ x) {
    __shared__ float As[64 * 68];
    __shared__ float Bs[64 * 68];
    __shared__ float sxi[64], sxj[64];
    int b = blockIdx.y;
    int t = blockIdx.x;
    int ti = 0;
    while (t >= 36 - ti) { t -= 36 - ti; ti++; }
    int tj = ti + t;
    int i0 = ti * 64, j0 = tj * 64;
    const float* xb = x + (size_t)b * NN * CC;
    int tid = threadIdx.x;

    for (int k = tid; k < 64 * 16; k += 64) {
        int r = k >> 4, c4 = (k & 15) << 2;
        *(float4*)(&As[r * 68 + c4]) = *(const float4*)(xb + (size_t)(i0 + r) * CC + c4);
        *(float4*)(&Bs[r * 68 + c4]) = *(const float4*)(xb + (size_t)(j0 + r) * CC + c4);
    }
    sxi[tid] = g_xsq[b * NN + i0 + tid];
    sxj[tid] = g_xsq[b * NN + j0 + tid];
    __syncthreads();

    int tx = tid & 7, ty = tid >> 3;
    float acc[8][8];
    #pragma unroll
    for (int i = 0; i < 8; i++)
        #pragma unroll
        for (int j = 0; j < 8; j++) acc[i][j] = 0.f;

    #pragma unroll 2
    for (int c = 0; c < 64; c += 4) {
        float4 a[8], bb[8];
        #pragma unroll
        for (int u = 0; u < 8; u++) {
            a[u]  = *(const float4*)(&As[(ty + 8 * u) * 68 + c]);
            bb[u] = *(const float4*)(&Bs[(tx + 8 * u) * 68 + c]);
        }
        #pragma unroll
        for (int i = 0; i < 8; i++)
            #pragma unroll
            for (int j = 0; j < 8; j++)
                acc[i][j] += a[i].x * bb[j].x + a[i].y * bb[j].y +
                             a[i].z * bb[j].z + a[i].w * bb[j].w;
    }

    float xi[8], xj[8];
    #pragma unroll
    for (int u = 0; u < 8; u++) { xi[u] = sxi[ty + 8 * u]; xj[u] = sxj[tx + 8 * u]; }
    __syncthreads();
    unsigned* S = (unsigned*)As;           // 64x65 staging
    #pragma unroll
    for (int i = 0; i < 8; i++)
        #pragma unroll
        for (int j = 0; j < 8; j++) {
            float v = (xi[i] - 2.f * acc[i][j]) + xj[j];
            S[(ty + 8 * i) * 65 + (tx + 8 * j)] = fkey(v);
        }
    __syncthreads();

    unsigned* dd = g_du + (size_t)b * NN * NN;
    #pragma unroll 4
    for (int r = 0; r < 64; r++)
        dd[(size_t)(i0 + r) * NN + j0 + tid] = S[r * 65 + tid];
    if (ti != tj) {
        #pragma unroll 4
        for (int r = 0; r < 64; r++)
            dd[(size_t)(j0 + r) * NN + i0 + tid] = S[tid * 65 + r];
    }
}

// ---------------- warp-level streaming top-K select --------------------------
#define SENT 0xffffffffffffffffULL

__device__ __forceinline__ void ins6(ull& k1, ull& k2, ull& k3, ull& k4,
                                     ull& k5, ull& k6, ull key) {
    if (key < k6) {
        if (key < k5) {
            k6 = k5;
            if (key < k4) {
                k5 = k4;
                if (key < k3) {
                    k4 = k3;
                    if (key < k2) {
                        k3 = k2;
                        if (key < k1) { k2 = k1; k1 = key; } else k2 = key;
                    } else k3 = key;
                } else k4 = key;
            } else k5 = key;
        } else k6 = key;
    }
}

// warp-wide u64 min via two hardware redux.sync ops (exact (value,index) order)
__device__ __forceinline__ ull warp_min64(ull k) {
    unsigned hi = (unsigned)(k >> 32);
    unsigned bhi = __reduce_min_sync(0xffffffffu, hi);
    unsigned lo = (hi == bhi) ? (unsigned)k : 0xffffffffu;
    unsigned blo = __reduce_min_sync(0xffffffffu, lo);
    return ((ull)bhi << 32) | blo;
}

// K extractions, smallest-first by (value, index). Per extracted idx calls SINK.
// 6-deep per-lane cache with cheap u32 gating; lane-local rescan is ~never hit.
template <class SINK>
__device__ __forceinline__ void run_select(int row, int lane, int K, SINK sink) {
    const uint4* __restrict__ dr = (const uint4*)(g_du + (size_t)row * NN);
    ull k1 = SENT, k2 = SENT, k3 = SENT, k4 = SENT, k5 = SENT, k6 = SENT;
    unsigned th = 0xffffffffu;
    #pragma unroll 1
    for (int t = 0; t < 18; t++) {
        uint4 v = dr[t * 32 + lane];
        unsigned base = t * 128 + lane * 4;
        unsigned mn = min(min(v.x, v.y), min(v.z, v.w));
        if (mn <= th) {
            if (v.x <= th) { ins6(k1,k2,k3,k4,k5,k6, ((ull)v.x << 32) | (base + 0)); th = (unsigned)(k6 >> 32); }
            if (v.y <= th) { ins6(k1,k2,k3,k4,k5,k6, ((ull)v.y << 32) | (base + 1)); th = (unsigned)(k6 >> 32); }
            if (v.z <= th) { ins6(k1,k2,k3,k4,k5,k6, ((ull)v.z << 32) | (base + 2)); th = (unsigned)(k6 >> 32); }
            if (v.w <= th) { ins6(k1,k2,k3,k4,k5,k6, ((ull)v.w << 32) | (base + 3)); th = (unsigned)(k6 >> 32); }
        }
    }
    ull last = 0;
    #pragma unroll 1
    for (int it = 0; it < K; it++) {
        if (k1 == SENT) {              // lane-local refill; probability ~6e-4
            th = 0xffffffffu;
            #pragma unroll 1
            for (int t = 0; t < 18; t++) {
                uint4 v = dr[t * 32 + lane];
                unsigned base = t * 128 + lane * 4;
                unsigned mn = min(min(v.x, v.y), min(v.z, v.w));
                if (mn <= th) {
                    ull a = ((ull)v.x << 32) | (base + 0);
                    ull b = ((ull)v.y << 32) | (base + 1);
                    ull c = ((ull)v.z << 32) | (base + 2);
                    ull d = ((ull)v.w << 32) | (base + 3);
                    if (v.x <= th && a > last) { ins6(k1,k2,k3,k4,k5,k6, a); th = (unsigned)(k6 >> 32); }
                    if (v.y <= th && b > last) { ins6(k1,k2,k3,k4,k5,k6, b); th = (unsigned)(k6 >> 32); }
                    if (v.z <= th && c > last) { ins6(k1,k2,k3,k4,k5,k6, c); th = (unsigned)(k6 >> 32); }
                    if (v.w <= th && d > last) { ins6(k1,k2,k3,k4,k5,k6, d); th = (unsigned)(k6 >> 32); }
                }
            }
        }
        ull bst = warp_min64(k1);
        last = bst;
        if (k1 == bst) { k1 = k2; k2 = k3; k3 = k4; k4 = k5; k5 = k6; k6 = SENT; }
        if (lane == 0) sink(it, (int)(unsigned)bst);
    }
}

// fast path: extract MSEL smallest per row; store list; count in-degree (top-11)
__global__ void __launch_bounds__(256) k_select() {
    int row  = blockIdx.x * 8 + (threadIdx.x >> 5);
    int lane = threadIdx.x & 31;
    int nb   = (row / NN) * NN;
    run_select(row, lane, MSEL, [&](int it, int bi) {
        g_top[(size_t)row * MSEL + it] = bi;
        if (it < KTOP) atomicAdd(&g_cnt1[nb + bi], 1);
    });
}

// cnt2 counting; rows with K > MSEL re-select fully into g_mem (slow path)
__global__ void __launch_bounds__(256) k_cnt2slow() {
    int row  = blockIdx.x * 8 + (threadIdx.x >> 5);
    int lane = threadIdx.x & 31;
    int K  = g_cnt1[row];
    int nb = (row / NN) * NN;
    if (K <= MSEL) {
        const int* lst = g_top + (size_t)row * MSEL;
        if (lane < K) atomicAdd(&g_cnt2[nb + lst[lane]], 1);
    } else {
        int* out = g_mem + (size_t)row * NN;
        run_select(row, lane, K, [&](int it, int bi) {
            out[it] = bi;
            atomicAdd(&g_cnt2[nb + bi], 1);
        });
    }
}

// ---------------- node normalization factors ---------------------------------
__device__ __forceinline__ int coverc(int r) {
    int lo = r - 4; if (lo < 0) lo = 0;
    int hi = r;     if (hi > 42) hi = 42;
    if (hi < lo) return 0;
    return hi / 2 - (lo + 1) / 2 + 1;
}

// ---------------- z = dv2 * (x W^T + b), dv2 computed inline -----------------
__global__ void __launch_bounds__(256) k_z(const float* __restrict__ x,
                                           const float* __restrict__ W,
                                           const float* __restrict__ bias) {
    __shared__ float Ws[64][65];
    __shared__ float xs[32][65];
    __shared__ float sb[64];
    __shared__ float sdvv[32];
    int tid = threadIdx.x;
    int base = blockIdx.x * 32;
    for (int k = tid; k < 64 * 64; k += 256) Ws[k >> 6][k & 63] = W[k];
    for (int k = tid; k < 32 * 64; k += 256) xs[k >> 6][k & 63] = x[(size_t)(base + (k >> 6)) * CC + (k & 63)];
    if (tid < 64) sb[tid] = bias[tid];
    if (tid < 32) {
        int row = base + tid;
        int n = row % NN;
        int deg = g_cnt2[row] + coverc(n / NODE_) * coverc(n % NODE_);
        float dv = rsqrtf((float)deg);
        g_dv2[row] = dv;
        sdvv[tid] = dv;
    }
    __syncthreads();

    int o = tid & 63, rg = tid >> 6;
    for (int r = rg; r < 32; r += 4) {
        float acc = sb[o];
        #pragma unroll
        for (int c = 0; c < 64; c++) acc += xs[r][c] * Ws[o][c];
        g_z[(size_t)(base + r) * CC + o] = sdvv[r] * acc;
    }
}

// ---------------- hyperedge gather / mean / scatter --------------------------
__global__ void __launch_bounds__(64) k_edge() {
    __shared__ int   sm[128];
    __shared__ float sdv[128];
    int e = blockIdx.x;
    int b = e / EPB;
    int le = e % EPB;
    int tid = threadIdx.x;
    int bNN = b * NN;
    int m;
    const int* lst = 0;
    if (le < NN) {
        int row = bNN + le;
        m = g_cnt1[row];
        lst = (m <= MSEL) ? (g_top + (size_t)row * MSEL) : (g_mem + (size_t)row * NN);
    } else {
        m = 25;
    }

    if (m <= 128) {
        if (le < NN) {
            for (int t = tid; t < m; t += 64) {
                int mi = lst[t];
                sm[t] = mi;
                sdv[t] = g_dv2[bNN + mi];
            }
        } else {
            int l = le - NN;
            int wi = l / NWIN, wj = l % NWIN;
            if (tid < 25) {
                int mi = (2 * wi + tid / 5) * NODE_ + (2 * wj + tid % 5);
                sm[tid] = mi;
                sdv[tid] = g_dv2[bNN + mi];
            }
        }
        __syncthreads();
        float acc = 0.f;
        for (int t = 0; t < m; t++)
            acc += g_z[((size_t)(bNN + sm[t])) * CC + tid];
        float u = acc * (1.0f / (float)m);
        for (int t = 0; t < m; t++)
            atomicAdd(&g_y[((size_t)(bNN + sm[t])) * CC + tid], sdv[t] * u);
    } else {
        float acc = 0.f;
        for (int base = 0; base < m; base += 128) {
            int cnt = min(128, m - base);
            __syncthreads();
            for (int t = tid; t < cnt; t += 64) sm[t] = lst[base + t];
            __syncthreads();
            for (int t = 0; t < cnt; t++)
                acc += g_z[((size_t)(bNN + sm[t])) * CC + tid];
        }
        float u = acc * (1.0f / (float)m);
        for (int base = 0; base < m; base += 128) {
            int cnt = min(128, m - base);
            __syncthreads();
            for (int t = tid; t < cnt; t += 64) {
                int mi = lst[base + t];
                sm[t] = mi;
                sdv[t] = g_dv2[bNN + mi];
            }
            __syncthreads();
            for (int t = 0; t < cnt; t++)
                atomicAdd(&g_y[((size_t)(bNN + sm[t])) * CC + tid], sdv[t] * u);
        }
    }
}

// ---------------- batchnorm statistics ---------------------------------------
__global__ void __launch_bounds__(256) k_bnstat() {
    __shared__ float red[256];
    int tid = threadIdx.x;
    int c = tid & 63, rg = tid >> 6;
    int r0 = blockIdx.x * 192;
    float s = 0.f, sq = 0.f;
    for (int r = r0 + rg; r < r0 + 192; r += 4) {
        float v = g_y[(size_t)r * CC + c];
        s += v; sq += v * v;
    }
    red[tid] = s; __syncthreads();
    if (rg == 0) atomicAdd(&g_bns[c], red[tid] + red[tid + 64] + red[tid + 128] + red[tid + 192]);
    __syncthreads();
    red[tid] = sq; __syncthreads();
    if (rg == 0) atomicAdd(&g_bns[64 + c], red[tid] + red[tid + 64] + red[tid + 128] + red[tid + 192]);
}

// ---------------- normalize + relu + residual --------------------------------
__global__ void __launch_bounds__(256) k_final(const float* __restrict__ x,
                                               const float* __restrict__ gamma,
                                               const float* __restrict__ beta,
                                               float* __restrict__ out) {
    __shared__ float sscale[64], sshift[64];
    int tid = threadIdx.x;
    if (tid < 64) {
        float mean = g_bns[tid] * (1.f / (float)BN);
        float var = g_bns[64 + tid] * (1.f / (float)BN) - mean * mean;
        float inv = rsqrtf(var + BNEPS);
        sscale[tid] = gamma[tid] * inv;
        sshift[tid] = beta[tid] - gamma[tid] * mean * inv;
    }
    __syncthreads();
    int idx = blockIdx.x * 256 + tid;
    int c = idx & 63;
    float v = g_y[idx] * sscale[c] + sshift[c];
    out[idx] = fmaxf(v, 0.f) + x[idx];
}

// ---------------- launch -----------------------------------------------------
extern "C" void kernel_launch(void* const* d_in, const int* in_sizes, int n_in,
                              void* d_out, int out_size) {
    const float* x     = (const float*)d_in[0];
    const float* W     = (const float*)d_in[1];
    const float* bias  = (const float*)d_in[2];
    const float* gamma = (const float*)d_in[3];
    const float* beta  = (const float*)d_in[4];
    float* out = (float*)d_out;
    (void)in_sizes; (void)n_in; (void)out_size;

    k_init<<<1152, 256>>>(x);
    k_dist<<<dim3(666, BB), 64>>>(x);
    k_select<<<BN / 8, 256>>>();
    k_cnt2slow<<<BN / 8, 256>>>();
    k_z<<<BN / 32, 256>>>(x, W, bias);
    k_edge<<<BB * EPB, 64>>>();
    k_bnstat<<<48, 256>>>();
    k_final<<<(BN * CC) / 256, 256>>>(x, gamma, beta, out);
}

// round 6
// speedup vs baseline: 1.5603x; 1.4415x over previous
#include <cuda_runtime.h>

#define BB    4
#define NN    2304
#define CC    64
#define NODE_ 48
#define KTOP  11          // K_NEIGS + 1
#define NWIN  22
#define NLOC  484         // 22*22 local hyperedges
#define EPB   (NN + NLOC) // edges per batch = 2788
#define BN    (BB * NN)   // 9216
#define MSEL  32          // cached top-M per row (fast path)
#define BNEPS 1e-5f

typedef unsigned long long ull;

// ---------------- scratch (static device globals; no allocation) -------------
__device__ unsigned g_du[(size_t)BB * NN * NN]; // ordered-uint distance matrix
__device__ int   g_mem[(size_t)BB * NN * NN];   // slow-path member lists (K>MSEL)
__device__ int   g_top[(size_t)BN * MSEL];      // fast-path sorted top-M indices
__device__ int   g_cnt1[BN];                    // Dv: in-degree of 11-NN graph
__device__ int   g_cnt2[BN];                    // knn part of total node degree
__device__ float g_xsq[BN];
__device__ float g_dv2[BN];                     // DV^-0.5
__device__ float g_z[BN * CC];                  // dv2 * (xW^T + b)
__device__ float g_y[BN * CC];                  // conv output
__device__ float g_bns[2 * CC];                 // BN sum / sumsq
__device__ int   g_nslow;                       // slow-row queue
__device__ int   g_slowq[BN];

// ---------------- init: row norms + zeroing (fused) --------------------------
__global__ void __launch_bounds__(256) k_init(const float* __restrict__ x) {
    int idx = blockIdx.x * 256 + threadIdx.x;    // 1152 blocks
    int w = idx >> 5, lane = idx & 31;
    float a = x[w * CC + lane];
    float b = x[w * CC + 32 + lane];
    float s = a * a + b * b;
    #pragma unroll
    for (int o = 16; o; o >>= 1) s += __shfl_down_sync(0xffffffffu, s, o);
    if (lane == 0) g_xsq[w] = s;
    g_y[idx] = 0.f;
    g_y[idx + 294912] = 0.f;                     // BN*CC = 2 * 294912
    if (idx < BN) { g_cnt1[idx] = 0; g_cnt2[idx] = 0; }
    if (idx < 2 * CC) g_bns[idx] = 0.f;
    if (idx == 0) g_nslow = 0;
}

// float -> order-preserving uint32
__device__ __forceinline__ unsigned fkey(float v) {
    unsigned u = __float_as_uint(v);
    return u ^ ((unsigned)((int)u >> 31) | 0x80000000u);
}

// ---------------- pairwise squared distances: upper triangle only ------------
__global__ void __launch_bounds__(64) k_dist(const float* __restrict__ x) {
    __shared__ float As[64 * 68];
    __shared__ float Bs[64 * 68];
    __shared__ float sxi[64], sxj[64];
    int b = blockIdx.y;
    int t = blockIdx.x;
    int ti = 0;
    while (t >= 36 - ti) { t -= 36 - ti; ti++; }
    int tj = ti + t;
    int i0 = ti * 64, j0 = tj * 64;
    const float* xb = x + (size_t)b * NN * CC;
    int tid = threadIdx.x;

    for (int k = tid; k < 64 * 16; k += 64) {
        int r = k >> 4, c4 = (k & 15) << 2;
        *(float4*)(&As[r * 68 + c4]) = *(const float4*)(xb + (size_t)(i0 + r) * CC + c4);
        *(float4*)(&Bs[r * 68 + c4]) = *(const float4*)(xb + (size_t)(j0 + r) * CC + c4);
    }
    sxi[tid] = g_xsq[b * NN + i0 + tid];
    sxj[tid] = g_xsq[b * NN + j0 + tid];
    __syncthreads();

    int tx = tid & 7, ty = tid >> 3;
    float acc[8][8];
    #pragma unroll
    for (int i = 0; i < 8; i++)
        #pragma unroll
        for (int j = 0; j < 8; j++) acc[i][j] = 0.f;

    #pragma unroll 2
    for (int c = 0; c < 64; c += 4) {
        float4 a[8], bb[8];
        #pragma unroll
        for (int u = 0; u < 8; u++) {
            a[u]  = *(const float4*)(&As[(ty + 8 * u) * 68 + c]);
            bb[u] = *(const float4*)(&Bs[(tx + 8 * u) * 68 + c]);
        }
        #pragma unroll
        for (int i = 0; i < 8; i++)
            #pragma unroll
            for (int j = 0; j < 8; j++)
                acc[i][j] += a[i].x * bb[j].x + a[i].y * bb[j].y +
                             a[i].z * bb[j].z + a[i].w * bb[j].w;
    }

    float xi[8], xj[8];
    #pragma unroll
    for (int u = 0; u < 8; u++) { xi[u] = sxi[ty + 8 * u]; xj[u] = sxj[tx + 8 * u]; }
    __syncthreads();
    unsigned* S = (unsigned*)As;           // 64x65 staging
    #pragma unroll
    for (int i = 0; i < 8; i++)
        #pragma unroll
        for (int j = 0; j < 8; j++) {
            float v = (xi[i] - 2.f * acc[i][j]) + xj[j];
            S[(ty + 8 * i) * 65 + (tx + 8 * j)] = fkey(v);
        }
    __syncthreads();

    unsigned* dd = g_du + (size_t)b * NN * NN;
    #pragma unroll 4
    for (int r = 0; r < 64; r++)
        dd[(size_t)(i0 + r) * NN + j0 + tid] = S[r * 65 + tid];
    if (ti != tj) {
        #pragma unroll 4
        for (int r = 0; r < 64; r++)
            dd[(size_t)(j0 + r) * NN + i0 + tid] = S[tid * 65 + r];
    }
}

// ---------------- warp-level streaming top-32 select -------------------------
#define SENT 0xffffffffffffffffULL

__device__ __forceinline__ void ins6(ull& k1, ull& k2, ull& k3, ull& k4,
                                     ull& k5, ull& k6, ull key) {
    if (key < k6) {
        if (key < k5) {
            k6 = k5;
            if (key < k4) {
                k5 = k4;
                if (key < k3) {
                    k4 = k3;
                    if (key < k2) {
                        k3 = k2;
                        if (key < k1) { k2 = k1; k1 = key; } else k2 = key;
                    } else k3 = key;
                } else k4 = key;
            } else k5 = key;
        } else k6 = key;
    }
}

__device__ __forceinline__ ull warp_min64(ull k) {
    unsigned hi = (unsigned)(k >> 32);
    unsigned bhi = __reduce_min_sync(0xffffffffu, hi);
    unsigned lo = (hi == bhi) ? (unsigned)k : 0xffffffffu;
    unsigned blo = __reduce_min_sync(0xffffffffu, lo);
    return ((ull)bhi << 32) | blo;
}

// fast path: extract MSEL smallest per row; store list; count in-degree (top-11)
__global__ void __launch_bounds__(256) k_select() {
    int row  = blockIdx.x * 8 + (threadIdx.x >> 5);
    int lane = threadIdx.x & 31;
    int nb   = (row / NN) * NN;
    const uint4* __restrict__ dr = (const uint4*)(g_du + (size_t)row * NN);
    ull k1 = SENT, k2 = SENT, k3 = SENT, k4 = SENT, k5 = SENT, k6 = SENT;
    unsigned th = 0xffffffffu;
    #pragma unroll 1
    for (int t = 0; t < 18; t++) {
        uint4 v = dr[t * 32 + lane];
        unsigned base = t * 128 + lane * 4;
        unsigned mn = min(min(v.x, v.y), min(v.z, v.w));
        if (mn <= th) {
            if (v.x <= th) { ins6(k1,k2,k3,k4,k5,k6, ((ull)v.x << 32) | (base + 0)); th = (unsigned)(k6 >> 32); }
            if (v.y <= th) { ins6(k1,k2,k3,k4,k5,k6, ((ull)v.y << 32) | (base + 1)); th = (unsigned)(k6 >> 32); }
            if (v.z <= th) { ins6(k1,k2,k3,k4,k5,k6, ((ull)v.z << 32) | (base + 2)); th = (unsigned)(k6 >> 32); }
            if (v.w <= th) { ins6(k1,k2,k3,k4,k5,k6, ((ull)v.w << 32) | (base + 3)); th = (unsigned)(k6 >> 32); }
        }
    }
    ull last = 0;
    #pragma unroll 1
    for (int it = 0; it < MSEL; it++) {
        if (k1 == SENT) {              // lane-local refill; ~never taken
            th = 0xffffffffu;
            #pragma unroll 1
            for (int t = 0; t < 18; t++) {
                uint4 v = dr[t * 32 + lane];
                unsigned base = t * 128 + lane * 4;
                unsigned mn = min(min(v.x, v.y), min(v.z, v.w));
                if (mn <= th) {
                    ull a = ((ull)v.x << 32) | (base + 0);
                    ull b = ((ull)v.y << 32) | (base + 1);
                    ull c = ((ull)v.z << 32) | (base + 2);
                    ull d = ((ull)v.w << 32) | (base + 3);
                    if (v.x <= th && a > last) { ins6(k1,k2,k3,k4,k5,k6, a); th = (unsigned)(k6 >> 32); }
                    if (v.y <= th && b > last) { ins6(k1,k2,k3,k4,k5,k6, b); th = (unsigned)(k6 >> 32); }
                    if (v.z <= th && c > last) { ins6(k1,k2,k3,k4,k5,k6, c); th = (unsigned)(k6 >> 32); }
                    if (v.w <= th && d > last) { ins6(k1,k2,k3,k4,k5,k6, d); th = (unsigned)(k6 >> 32); }
                }
            }
        }
        ull bst = warp_min64(k1);
        last = bst;
        if (k1 == bst) { k1 = k2; k2 = k3; k3 = k4; k4 = k5; k5 = k6; k6 = SENT; }
        if (lane == 0) {
            int bi = (int)(unsigned)bst;
            g_top[(size_t)row * MSEL + it] = bi;
            if (it < KTOP) atomicAdd(&g_cnt1[nb + bi], 1);
        }
    }
}

// cnt2 counting for fast rows; enqueue rows with K > MSEL ---------------------
__global__ void __launch_bounds__(256) k_cnt2() {
    int row  = blockIdx.x * 8 + (threadIdx.x >> 5);
    int lane = threadIdx.x & 31;
    int K  = g_cnt1[row];
    int nb = (row / NN) * NN;
    if (K <= MSEL) {
        const int* lst = g_top + (size_t)row * MSEL;
        if (lane < K) atomicAdd(&g_cnt2[nb + lst[lane]], 1);
    } else if (lane == 0) {
        int q = atomicAdd(&g_nslow, 1);
        g_slowq[q] = row;
    }
}

// ---------------- slow rows: O(N) threshold selection per row ----------------
// One 256-thread block per queued row. Binary search the K-th order statistic
// of the u32 keys; members = {key < vK} + smallest-index fixup among {== vK}.
__global__ void __launch_bounds__(256) k_slowsel() {
    __shared__ unsigned sk[NN];
    __shared__ int sw[8];
    __shared__ int sbc;
    __shared__ int spos;
    int tid = threadIdx.x;
    int nslow = g_nslow;
    for (int qi = blockIdx.x; qi < nslow; qi += gridDim.x) {
        int row = g_slowq[qi];
        int nb = (row / NN) * NN;
        const unsigned* dr = g_du + (size_t)row * NN;
        for (int i = tid; i < NN; i += 256) sk[i] = dr[i];
        int K = g_cnt1[row];
        if (tid == 0) spos = 0;
        __syncthreads();

        unsigned lo = 0u, hi = 0xffffffffu;
        while (lo < hi) {
            unsigned mid = lo + ((hi - lo) >> 1);
            int c = 0;
            #pragma unroll
            for (int u = 0; u < 9; u++) c += (sk[tid + 256 * u] <= mid);
            c = __reduce_add_sync(0xffffffffu, c);
            if ((tid & 31) == 0) sw[tid >> 5] = c;
            __syncthreads();
            if (tid == 0) {
                int tot = 0;
                #pragma unroll
                for (int w = 0; w < 8; w++) tot += sw[w];
                sbc = tot;
            }
            __syncthreads();
            int tot = sbc;
            __syncthreads();
            if (tot >= K) hi = mid; else lo = mid + 1;
        }
        unsigned vK = lo;

        // strictly-less count
        {
            int c = 0;
            #pragma unroll
            for (int u = 0; u < 9; u++) c += (sk[tid + 256 * u] < vK);
            c = __reduce_add_sync(0xffffffffu, c);
            if ((tid & 31) == 0) sw[tid >> 5] = c;
            __syncthreads();
            if (tid == 0) {
                int tot = 0;
                #pragma unroll
                for (int w = 0; w < 8; w++) tot += sw[w];
                sbc = tot;
            }
            __syncthreads();
        }
        int c_lt = sbc;
        int need_eq = K - c_lt;

        int* out = g_mem + (size_t)row * NN;
        for (int i = tid; i < NN; i += 256) {
            if (sk[i] < vK) {
                int p = atomicAdd(&spos, 1);
                out[p] = i;
                atomicAdd(&g_cnt2[nb + i], 1);
            }
        }
        __syncthreads();

        int last = -1;
        for (int e = 0; e < need_eq; e++) {
            int mi = NN;
            #pragma unroll
            for (int u = 0; u < 9; u++) {
                int i = tid + 256 * u;
                if (sk[i] == vK && i > last && i < mi) mi = i;
            }
            mi = __reduce_min_sync(0xffffffffu, mi);
            if ((tid & 31) == 0) sw[tid >> 5] = mi;
            __syncthreads();
            if (tid == 0) {
                int m = sw[0];
                #pragma unroll
                for (int w = 1; w < 8; w++) m = min(m, sw[w]);
                sbc = m;
            }
            __syncthreads();
            mi = sbc;
            if (tid == 0) {
                out[c_lt + e] = mi;
                atomicAdd(&g_cnt2[nb + mi], 1);
            }
            last = mi;
            __syncthreads();
        }
        __syncthreads();
    }
}

// ---------------- node normalization factors ---------------------------------
__device__ __forceinline__ int coverc(int r) {
    int lo = r - 4; if (lo < 0) lo = 0;
    int hi = r;     if (hi > 42) hi = 42;
    if (hi < lo) return 0;
    return hi / 2 - (lo + 1) / 2 + 1;
}

// ---------------- z = dv2 * (x W^T + b), dv2 computed inline -----------------
__global__ void __launch_bounds__(256) k_z(const float* __restrict__ x,
                                           const float* __restrict__ W,
                                           const float* __restrict__ bias) {
    __shared__ float Ws[64][65];
    __shared__ float xs[32][65];
    __shared__ float sb[64];
    __shared__ float sdvv[32];
    int tid = threadIdx.x;
    int base = blockIdx.x * 32;
    for (int k = tid; k < 64 * 64; k += 256) Ws[k >> 6][k & 63] = W[k];
    for (int k = tid; k < 32 * 64; k += 256) xs[k >> 6][k & 63] = x[(size_t)(base + (k >> 6)) * CC + (k & 63)];
    if (tid < 64) sb[tid] = bias[tid];
    if (tid < 32) {
        int row = base + tid;
        int n = row % NN;
        int deg = g_cnt2[row] + coverc(n / NODE_) * coverc(n % NODE_);
        float dv = rsqrtf((float)deg);
        g_dv2[row] = dv;
        sdvv[tid] = dv;
    }
    __syncthreads();

    int o = tid & 63, rg = tid >> 6;
    for (int r = rg; r < 32; r += 4) {
        float acc = sb[o];
        #pragma unroll
        for (int c = 0; c < 64; c++) acc += xs[r][c] * Ws[o][c];
        g_z[(size_t)(base + r) * CC + o] = sdvv[r] * acc;
    }
}

// ---------------- hyperedge gather / mean / scatter --------------------------
__global__ void __launch_bounds__(64) k_edge() {
    __shared__ int   sm[128];
    __shared__ float sdv[128];
    int e = blockIdx.x;
    int b = e / EPB;
    int le = e % EPB;
    int tid = threadIdx.x;
    int bNN = b * NN;
    int m;
    const int* lst = 0;
    if (le < NN) {
        int row = bNN + le;
        m = g_cnt1[row];
        lst = (m <= MSEL) ? (g_top + (size_t)row * MSEL) : (g_mem + (size_t)row * NN);
    } else {
        m = 25;
    }

    if (m <= 128) {
        if (le < NN) {
            for (int t = tid; t < m; t += 64) {
                int mi = lst[t];
                sm[t] = mi;
                sdv[t] = g_dv2[bNN + mi];
            }
        } else {
            int l = le - NN;
            int wi = l / NWIN, wj = l % NWIN;
            if (tid < 25) {
                int mi = (2 * wi + tid / 5) * NODE_ + (2 * wj + tid % 5);
                sm[tid] = mi;
                sdv[tid] = g_dv2[bNN + mi];
            }
        }
        __syncthreads();
        float acc = 0.f;
        for (int t = 0; t < m; t++)
            acc += g_z[((size_t)(bNN + sm[t])) * CC + tid];
        float u = acc * (1.0f / (float)m);
        for (int t = 0; t < m; t++)
            atomicAdd(&g_y[((size_t)(bNN + sm[t])) * CC + tid], sdv[t] * u);
    } else {
        float acc = 0.f;
        for (int base = 0; base < m; base += 128) {
            int cnt = min(128, m - base);
            __syncthreads();
            for (int t = tid; t < cnt; t += 64) sm[t] = lst[base + t];
            __syncthreads();
            for (int t = 0; t < cnt; t++)
                acc += g_z[((size_t)(bNN + sm[t])) * CC + tid];
        }
        float u = acc * (1.0f / (float)m);
        for (int base = 0; base < m; base += 128) {
            int cnt = min(128, m - base);
            __syncthreads();
            for (int t = tid; t < cnt; t += 64) {
                int mi = lst[base + t];
                sm[t] = mi;
                sdv[t] = g_dv2[bNN + mi];
            }
            __syncthreads();
            for (int t = 0; t < cnt; t++)
                atomicAdd(&g_y[((size_t)(bNN + sm[t])) * CC + tid], sdv[t] * u);
        }
    }
}

// ---------------- batchnorm statistics ---------------------------------------
__global__ void __launch_bounds__(256) k_bnstat() {
    __shared__ float red[256];
    int tid = threadIdx.x;
    int c = tid & 63, rg = tid >> 6;
    int r0 = blockIdx.x * 192;
    float s = 0.f, sq = 0.f;
    for (int r = r0 + rg; r < r0 + 192; r += 4) {
        float v = g_y[(size_t)r * CC + c];
        s += v; sq += v * v;
    }
    red[tid] = s; __syncthreads();
    if (rg == 0) atomicAdd(&g_bns[c], red[tid] + red[tid + 64] + red[tid + 128] + red[tid + 192]);
    __syncthreads();
    red[tid] = sq; __syncthreads();
    if (rg == 0) atomicAdd(&g_bns[64 + c], red[tid] + red[tid + 64] + red[tid + 128] + red[tid + 192]);
}

// ---------------- normalize + relu + residual --------------------------------
__global__ void __launch_bounds__(256) k_final(const float* __restrict__ x,
                                               const float* __restrict__ gamma,
                                               const float* __restrict__ beta,
                                               float* __restrict__ out) {
    __shared__ float sscale[64], sshift[64];
    int tid = threadIdx.x;
    if (tid < 64) {
        float mean = g_bns[tid] * (1.f / (float)BN);
        float var = g_bns[64 + tid] * (1.f / (float)BN) - mean * mean;
        float inv = rsqrtf(var + BNEPS);
        sscale[tid] = gamma[tid] * inv;
        sshift[tid] = beta[tid] - gamma[tid] * mean * inv;
    }
    __syncthreads();
    int idx = blockIdx.x * 256 + tid;
    int c = idx & 63;
    float v = g_y[idx] * sscale[c] + sshift[c];
    out[idx] = fmaxf(v, 0.f) + x[idx];
}

// ---------------- launch -----------------------------------------------------
extern "C" void kernel_launch(void* const* d_in, const int* in_sizes, int n_in,
                              void* d_out, int out_size) {
    const float* x     = (const float*)d_in[0];
    const float* W     = (const float*)d_in[1];
    const float* bias  = (const float*)d_in[2];
    const float* gamma = (const float*)d_in[3];
    const float* beta  = (const float*)d_in[4];
    float* out = (float*)d_out;
    (void)in_sizes; (void)n_in; (void)out_size;

    k_init<<<1152, 256>>>(x);
    k_dist<<<dim3(666, BB), 64>>>(x);
    k_select<<<BN / 8, 256>>>();
    k_cnt2<<<BN / 8, 256>>>();
    k_slowsel<<<148, 256>>>();
    k_z<<<BN / 32, 256>>>(x, W, bias);
    k_edge<<<BB * EPB, 64>>>();
    k_bnstat<<<48, 256>>>();
    k_final<<<(BN * CC) / 256, 256>>>(x, gamma, beta, out);
}